// round 12
// baseline (speedup 1.0000x reference)
#include <cuda_runtime.h>
#include <stdint.h>
#include <math.h>

// Problem shape (fixed by dataset): B=8, S=2048, H=2048
#define M_DIM 16384
#define H_DIM 2048

// Static device scratch (allowed; no runtime allocation)
__device__ float g_xr[(size_t)M_DIM * H_DIM];    // rna(x)            [m][h]
__device__ float g_xt[(size_t)H_DIM * M_DIM];    // rna(x)^T          [h][m]
__device__ float g_ct[(size_t)H_DIM * M_DIM];    // rna(combined)^T   [n][m]
__device__ float g_wsum[(size_t)H_DIM * H_DIM];  // rna(Wf + Wp)      [n][k]
__device__ float g_c2p[4][(size_t)H_DIM * H_DIM];// split-K partials of x^T @ combined
__device__ float g_partials[1024];
__device__ float g_scale;

// ---------------------------------------------------------------------------
// helpers
// ---------------------------------------------------------------------------
__device__ __forceinline__ uint32_t smem_u32(const void* p) {
    uint32_t a;
    asm("{ .reg .u64 t; cvta.to.shared.u64 t, %1; cvt.u32.u64 %0, t; }" : "=r"(a) : "l"(p));
    return a;
}
__device__ __forceinline__ uint32_t f2tf32(float f) {
    uint32_t r;
    asm("cvt.rna.tf32.f32 %0, %1;" : "=r"(r) : "f"(f));
    return r;
}
__device__ __forceinline__ uint4 tf32x4(float4 v) {
    uint4 r;
    r.x = f2tf32(v.x); r.y = f2tf32(v.y); r.z = f2tf32(v.z); r.w = f2tf32(v.w);
    return r;
}
__device__ __forceinline__ void cp16(uint32_t s, const void* g) {
    asm volatile("cp.async.cg.shared.global [%0], [%1], 16;" :: "r"(s), "l"(g) : "memory");
}
#define CP_COMMIT() asm volatile("cp.async.commit_group;" ::: "memory")
#define CP_WAIT2()  asm volatile("cp.async.wait_group 2;" ::: "memory")

__device__ __forceinline__ void ldsm4(uint32_t* r, uint32_t addr) {
    asm volatile("ldmatrix.sync.aligned.m8n8.x4.shared.b16 {%0,%1,%2,%3}, [%4];"
                 : "=r"(r[0]), "=r"(r[1]), "=r"(r[2]), "=r"(r[3]) : "r"(addr));
}

#define MMA_TF32(d, a0, a1, a2, a3, b0, b1)                                   \
    asm volatile(                                                             \
        "mma.sync.aligned.m16n8k8.row.col.f32.tf32.tf32.f32 "                 \
        "{%0,%1,%2,%3}, {%4,%5,%6,%7}, {%8,%9}, {%0,%1,%2,%3};\n"             \
        : "+f"((d)[0]), "+f"((d)[1]), "+f"((d)[2]), "+f"((d)[3])              \
        : "r"(a0), "r"(a1), "r"(a2), "r"(a3), "r"(b0), "r"(b1))

// Stage layout (BK = 16): 4 stages x 16KB. Within a stage:
//   A at +0:    4 quad-regions of 2KB; row r of quad q at q*2048 + ((r ^ 2q)*16)
//   B at +8192: same layout
#define STAGE_BYTES 16384
#define NSTAGE 4
#define SMEM_G1 67584                      // 128*132*4 epi buffer > 4 stages (65536)
#define SMEM_G2 (NSTAGE * STAGE_BYTES)     // 65536

// ---------------------------------------------------------------------------
// prep kernels
// ---------------------------------------------------------------------------
__global__ __launch_bounds__(256) void prep_w(const float* __restrict__ wf,
                                              const float* __restrict__ wpl) {
    int i4 = blockIdx.x * 256 + threadIdx.x;  // 1,048,576 float4
    float4 a = ((const float4*)wf)[i4];
    float4 b = ((const float4*)wpl)[i4];
    float4 s = make_float4(a.x + b.x, a.y + b.y, a.z + b.z, a.w + b.w);
    ((uint4*)g_wsum)[i4] = tf32x4(s);
}

// 32x32 tiles: write rna(x) (same layout) and rna(x)^T
__global__ __launch_bounds__(256) void prep_x(const float* __restrict__ x) {
    __shared__ float tsm[32][33];
    const int tx = threadIdx.x, ty = threadIdx.y;
    const int p0 = blockIdx.x * 32, m0 = blockIdx.y * 32;
#pragma unroll
    for (int i = 0; i < 4; i++) {
        const int m = m0 + ty + i * 8;
        float v = x[(size_t)m * H_DIM + p0 + tx];
        float r = __uint_as_float(f2tf32(v));
        g_xr[(size_t)m * H_DIM + p0 + tx] = r;
        tsm[ty + i * 8][tx] = r;
    }
    __syncthreads();
#pragma unroll
    for (int i = 0; i < 4; i++) {
        const int p = p0 + ty + i * 8;
        g_xt[(size_t)p * M_DIM + m0 + tx] = tsm[tx][ty + i * 8];
    }
}

// ---------------------------------------------------------------------------
// core mainloop pieces (512 threads: 4x4 warp grid, 32x32 warp tiles)
// ---------------------------------------------------------------------------
struct Frags {
    uint32_t rowA16[2];   // (wm + mi*16 + (lane&15)) * 16
    uint32_t rowB16[2];   // (wn + (2P + ((lane>>3)>>1))*8 + (lane&7)) * 16
    uint32_t qa, qb;      // lane>>4 ; (lane>>3)&1
};

__device__ __forceinline__ void init_frags(Frags& F, int lane, int wm, int wn) {
    const int G = lane >> 3;
#pragma unroll
    for (int mi = 0; mi < 2; mi++)
        F.rowA16[mi] = (uint32_t)(wm + mi * 16 + (lane & 15)) * 16u;
#pragma unroll
    for (int P = 0; P < 2; P++)
        F.rowB16[P] = (uint32_t)(wn + (2 * P + (G >> 1)) * 8 + (lane & 7)) * 16u;
    F.qa = (uint32_t)(lane >> 4);
    F.qb = (uint32_t)(G & 1);
}

// One 16-k stage: 2 ks8 sub-steps; transient fragment registers only.
__device__ __forceinline__ void compute_stage(const Frags& F, uint32_t stg,
                                              float acc[2][4][4]) {
#pragma unroll
    for (int ks8 = 0; ks8 < 2; ks8++) {
        const uint32_t aq = (uint32_t)(ks8 * 2) + F.qa;
        const uint32_t bq = (uint32_t)(ks8 * 2) + F.qb;
        uint32_t af[2][4], bf[2][4];
#pragma unroll
        for (int mi = 0; mi < 2; mi++)
            ldsm4(af[mi], stg + aq * 2048u + (F.rowA16[mi] ^ (aq << 5)));
#pragma unroll
        for (int P = 0; P < 2; P++)
            ldsm4(bf[P], stg + 8192u + bq * 2048u + (F.rowB16[P] ^ (bq << 5)));
#pragma unroll
        for (int mi = 0; mi < 2; mi++)
#pragma unroll
            for (int P = 0; P < 2; P++) {
                MMA_TF32(acc[mi][2 * P],     af[mi][0], af[mi][1], af[mi][2], af[mi][3],
                         bf[P][0], bf[P][1]);
                MMA_TF32(acc[mi][2 * P + 1], af[mi][0], af[mi][1], af[mi][2], af[mi][3],
                         bf[P][2], bf[P][3]);
            }
    }
}

// Loader (512 threads): lq = tid&3 (k-quad), lr = tid>>2 (0..127) -> 1 cp16 A + 1 cp16 B
#define ISSUE_STAGE(kt, gA, gB, sA0)  do {                                 \
        const uint32_t st_ = (uint32_t)((kt) & (NSTAGE - 1)) * STAGE_BYTES; \
        const size_t ko_ = (size_t)(kt) * 16;                              \
        cp16((sA0) + st_,          (gA) + ko_);                            \
        cp16((sA0) + st_ + 8192u,  (gB) + ko_);                            \
    } while (0)

// ---------------------------------------------------------------------------
// GEMM1: combined[m,n] = g_xr[m,:] . g_wsum[n,:] + bias[n]
// Writes: C (fp32, [m][n]) and g_ct (rna(combined)^T, [n][m])
// ---------------------------------------------------------------------------
__global__ __launch_bounds__(512, 2) void gemm1_k(
    const float* __restrict__ bias, float* __restrict__ C)
{
    extern __shared__ char sm[];
    const uint32_t sbase = smem_u32(sm);
    const int tid = threadIdx.x, lane = tid & 31, warp = tid >> 5;
    const int g = lane >> 2, t = lane & 3;
    const int wm = (warp >> 2) * 32, wn = (warp & 3) * 32;
    const int m0 = blockIdx.y * 128, n0 = blockIdx.x * 128;

    const int lq = tid & 3, lr = tid >> 2;  // k-quad, row 0..127
    const float* gA = g_xr   + (size_t)(m0 + lr) * H_DIM + lq * 4;
    const float* gB = g_wsum + (size_t)(n0 + lr) * H_DIM + lq * 4;
    const uint32_t sA0 = sbase + (uint32_t)lq * 2048u + (uint32_t)((lr ^ (2 * lq)) * 16);

    Frags F;
    init_frags(F, lane, wm, wn);

    float acc[2][4][4];
#pragma unroll
    for (int mi = 0; mi < 2; mi++)
#pragma unroll
        for (int ni = 0; ni < 4; ni++)
#pragma unroll
            for (int c = 0; c < 4; c++) acc[mi][ni][c] = 0.0f;

    ISSUE_STAGE(0, gA, gB, sA0); CP_COMMIT();
    ISSUE_STAGE(1, gA, gB, sA0); CP_COMMIT();
    ISSUE_STAGE(2, gA, gB, sA0); CP_COMMIT();

    const int KT = H_DIM / 16;  // 128
    for (int kt = 0; kt < KT; kt++) {
        CP_WAIT2();
        __syncthreads();
        if (kt + 3 < KT) { ISSUE_STAGE(kt + 3, gA, gB, sA0); }
        CP_COMMIT();
        compute_stage(F, sbase + (uint32_t)(kt & (NSTAGE - 1)) * STAGE_BYTES, acc);
    }

    __syncthreads();  // stages free -> reuse smem for transpose

    // Epilogue: add bias; store combined; stash rounded values transposed in smem
    float* Csm = (float*)sm;  // [n 128][m 132] words (pad 4 -> conflict-free)
#pragma unroll
    for (int ni = 0; ni < 4; ni++) {
        const int n = wn + ni * 8 + 2 * t;
        const float2 bv = *(const float2*)&bias[n0 + n];
#pragma unroll
        for (int mi = 0; mi < 2; mi++) {
            const int m = wm + mi * 16 + g;
            float v0 = acc[mi][ni][0] + bv.x, v1 = acc[mi][ni][1] + bv.y;
            float v2 = acc[mi][ni][2] + bv.x, v3 = acc[mi][ni][3] + bv.y;
            *(float2*)&C[(size_t)(m0 + m) * H_DIM + n0 + n]     = make_float2(v0, v1);
            *(float2*)&C[(size_t)(m0 + m + 8) * H_DIM + n0 + n] = make_float2(v2, v3);
            Csm[n * 132 + m]           = __uint_as_float(f2tf32(v0));
            Csm[(n + 1) * 132 + m]     = __uint_as_float(f2tf32(v1));
            Csm[n * 132 + m + 8]       = __uint_as_float(f2tf32(v2));
            Csm[(n + 1) * 132 + m + 8] = __uint_as_float(f2tf32(v3));
        }
    }
    __syncthreads();
    // Coalesced store of the transposed tile
    for (int idx = tid; idx < 128 * 32; idx += 512) {
        const int nrow = idx >> 5, mq = idx & 31;
        float4 v = *(const float4*)&Csm[nrow * 132 + mq * 4];
        *(float4*)&g_ct[(size_t)(n0 + nrow) * M_DIM + m0 + mq * 4] = v;
    }
}

// ---------------------------------------------------------------------------
// GEMM2 (split-K=4): g_c2p[sp][p,q] = sum_{m in split} g_xt[p,m]*g_ct[q,m]
// ---------------------------------------------------------------------------
__global__ __launch_bounds__(512, 2) void gemm2_k()
{
    extern __shared__ char sm[];
    const uint32_t sbase = smem_u32(sm);
    const int tid = threadIdx.x, lane = tid & 31, warp = tid >> 5;
    const int g = lane >> 2, t = lane & 3;
    const int wm = (warp >> 2) * 32, wn = (warp & 3) * 32;
    const int p0 = blockIdx.y * 128, q0 = blockIdx.x * 128;
    const int sp = blockIdx.z;
    const int mbase = sp * (M_DIM / 4);

    const int lq = tid & 3, lr = tid >> 2;
    const float* gA = g_xt + (size_t)(p0 + lr) * M_DIM + mbase + lq * 4;
    const float* gB = g_ct + (size_t)(q0 + lr) * M_DIM + mbase + lq * 4;
    const uint32_t sA0 = sbase + (uint32_t)lq * 2048u + (uint32_t)((lr ^ (2 * lq)) * 16);

    Frags F;
    init_frags(F, lane, wm, wn);

    float acc[2][4][4];
#pragma unroll
    for (int mi = 0; mi < 2; mi++)
#pragma unroll
        for (int ni = 0; ni < 4; ni++)
#pragma unroll
            for (int c = 0; c < 4; c++) acc[mi][ni][c] = 0.0f;

    ISSUE_STAGE(0, gA, gB, sA0); CP_COMMIT();
    ISSUE_STAGE(1, gA, gB, sA0); CP_COMMIT();
    ISSUE_STAGE(2, gA, gB, sA0); CP_COMMIT();

    const int KT = (M_DIM / 4) / 16;  // 256
    for (int kt = 0; kt < KT; kt++) {
        CP_WAIT2();
        __syncthreads();
        if (kt + 3 < KT) { ISSUE_STAGE(kt + 3, gA, gB, sA0); }
        CP_COMMIT();
        compute_stage(F, sbase + (uint32_t)(kt & (NSTAGE - 1)) * STAGE_BYTES, acc);
    }

    float* dst = g_c2p[sp];
#pragma unroll
    for (int ni = 0; ni < 4; ni++) {
        const int q = q0 + wn + ni * 8 + 2 * t;
#pragma unroll
        for (int mi = 0; mi < 2; mi++) {
            const int p = p0 + wm + mi * 16 + g;
            *(float2*)&dst[(size_t)p * H_DIM + q]       = make_float2(acc[mi][ni][0], acc[mi][ni][1]);
            *(float2*)&dst[(size_t)(p + 8) * H_DIM + q] = make_float2(acc[mi][ni][2], acc[mi][ni][3]);
        }
    }
}

// ---------------------------------------------------------------------------
// Combine split-K partials; Frobenius norm; conditional scale
// ---------------------------------------------------------------------------
__global__ __launch_bounds__(256) void combine_kernel(
    const float* __restrict__ wpl, const float* __restrict__ pr,
    const float* __restrict__ hs, float* __restrict__ outw)
{
    __shared__ float red[8];
    const int tid = threadIdx.x;
    const float f = pr[0] * hs[0] * (1.0f / (float)M_DIM);
    float ssq = 0.0f;
#pragma unroll
    for (int r = 0; r < 4; r++) {
        const int i4 = blockIdx.x * 1024 + r * 256 + tid;
        float4 a = ((const float4*)g_c2p[0])[i4];
        float4 b = ((const float4*)g_c2p[1])[i4];
        float4 c = ((const float4*)g_c2p[2])[i4];
        float4 d = ((const float4*)g_c2p[3])[i4];
        float4 w = ((const float4*)wpl)[i4];
        float4 v;
        v.x = w.x + f * (a.x + b.x + c.x + d.x);
        v.y = w.y + f * (a.y + b.y + c.y + d.y);
        v.z = w.z + f * (a.z + b.z + c.z + d.z);
        v.w = w.w + f * (a.w + b.w + c.w + d.w);
        ((float4*)outw)[i4] = v;
        ssq += v.x * v.x + v.y * v.y + v.z * v.z + v.w * v.w;
    }
#pragma unroll
    for (int o = 16; o; o >>= 1) ssq += __shfl_xor_sync(0xffffffffu, ssq, o);
    if ((tid & 31) == 0) red[tid >> 5] = ssq;
    __syncthreads();
    if (tid == 0) {
        float s = 0.0f;
#pragma unroll
        for (int w = 0; w < 8; w++) s += red[w];
        g_partials[blockIdx.x] = s;
    }
}

__global__ void finalize_kernel() {
    const int tid = threadIdx.x;
    __shared__ float red[8];
    float v = g_partials[tid] + g_partials[tid + 256] +
              g_partials[tid + 512] + g_partials[tid + 768];
#pragma unroll
    for (int o = 16; o; o >>= 1) v += __shfl_xor_sync(0xffffffffu, v, o);
    if ((tid & 31) == 0) red[tid >> 5] = v;
    __syncthreads();
    if (tid == 0) {
        float s = 0.0f;
#pragma unroll
        for (int w = 0; w < 8; w++) s += red[w];
        const float n = sqrtf(s);
        g_scale = (n > 1.0f) ? (1.0f / n) : 1.0f;
    }
}

__global__ void scale_kernel(float* __restrict__ w) {
    const float s = g_scale;
    const int n4 = (H_DIM * H_DIM) / 4;
    float4* w4 = (float4*)w;
    for (int i = blockIdx.x * blockDim.x + threadIdx.x; i < n4;
         i += gridDim.x * blockDim.x) {
        float4 v = w4[i];
        v.x *= s; v.y *= s; v.z *= s; v.w *= s;
        w4[i] = v;
    }
}

// ---------------------------------------------------------------------------
// Inputs: x, plastic_weights, plasticity_rate, fixed_w, fixed_b, hebbian_strength
// Output: combined [16384,2048] ++ new_w [2048,2048]
// ---------------------------------------------------------------------------
extern "C" void kernel_launch(void* const* d_in, const int* in_sizes, int n_in,
                              void* d_out, int out_size)
{
    const float* x  = (const float*)d_in[0];
    const float* wp = (const float*)d_in[1];
    const float* pr = (const float*)d_in[2];
    const float* wf = (const float*)d_in[3];
    const float* fb = (const float*)d_in[4];
    const float* hs = (const float*)d_in[5];

    float* combined = (float*)d_out;
    float* outw     = combined + (size_t)M_DIM * H_DIM;

    cudaFuncSetAttribute(gemm1_k, cudaFuncAttributeMaxDynamicSharedMemorySize, SMEM_G1);
    cudaFuncSetAttribute(gemm2_k, cudaFuncAttributeMaxDynamicSharedMemorySize, SMEM_G2);

    prep_w<<<4096, 256>>>(wf, wp);
    prep_x<<<dim3(H_DIM / 32, M_DIM / 32), dim3(32, 8)>>>(x);

    gemm1_k<<<dim3(16, 128), 512, SMEM_G1>>>(fb, combined);
    gemm2_k<<<dim3(16, 16, 4), 512, SMEM_G2>>>();

    combine_kernel<<<1024, 256>>>(wp, pr, hs, outw);
    finalize_kernel<<<1, 256>>>();
    scale_kernel<<<2048, 256>>>(outw);
}

// round 13
// speedup vs baseline: 1.4270x; 1.4270x over previous
#include <cuda_runtime.h>
#include <stdint.h>
#include <math.h>

// Problem shape (fixed by dataset): B=8, S=2048, H=2048
#define M_DIM 16384
#define H_DIM 2048

// Static device scratch (allowed; no runtime allocation)
__device__ float g_xr[(size_t)M_DIM * H_DIM];    // rna(x)         [m][h]
__device__ float g_xt[(size_t)H_DIM * M_DIM];    // rna(x)^T       [h][m]
__device__ float g_wsum[(size_t)H_DIM * H_DIM];  // rna(Wf + Wp)   [n][k]
__device__ float g_gp[8][(size_t)H_DIM * H_DIM]; // Gram split-K partials (lower-tri blocks)
__device__ float g_gram[(size_t)H_DIM * H_DIM];  // rna(x^T x), full (mirrored)
__device__ float g_colsum[H_DIM];                // sum_m x[m][h]
__device__ float g_partials[256];
__device__ float g_scale;

// ---------------------------------------------------------------------------
// helpers
// ---------------------------------------------------------------------------
__device__ __forceinline__ uint32_t smem_u32(const void* p) {
    uint32_t a;
    asm("{ .reg .u64 t; cvta.to.shared.u64 t, %1; cvt.u32.u64 %0, t; }" : "=r"(a) : "l"(p));
    return a;
}
__device__ __forceinline__ uint32_t f2tf32(float f) {
    uint32_t r;
    asm("cvt.rna.tf32.f32 %0, %1;" : "=r"(r) : "f"(f));
    return r;
}
__device__ __forceinline__ uint4 tf32x4(float4 v) {
    uint4 r;
    r.x = f2tf32(v.x); r.y = f2tf32(v.y); r.z = f2tf32(v.z); r.w = f2tf32(v.w);
    return r;
}
__device__ __forceinline__ void cp16(uint32_t s, const void* g) {
    asm volatile("cp.async.cg.shared.global [%0], [%1], 16;" :: "r"(s), "l"(g) : "memory");
}
#define CP_COMMIT() asm volatile("cp.async.commit_group;" ::: "memory")
#define CP_WAIT2()  asm volatile("cp.async.wait_group 2;" ::: "memory")

__device__ __forceinline__ void ldsm4(uint32_t* r, uint32_t addr) {
    asm volatile("ldmatrix.sync.aligned.m8n8.x4.shared.b16 {%0,%1,%2,%3}, [%4];"
                 : "=r"(r[0]), "=r"(r[1]), "=r"(r[2]), "=r"(r[3]) : "r"(addr));
}

#define MMA_TF32(d, a0, a1, a2, a3, b0, b1)                                   \
    asm volatile(                                                             \
        "mma.sync.aligned.m16n8k8.row.col.f32.tf32.tf32.f32 "                 \
        "{%0,%1,%2,%3}, {%4,%5,%6,%7}, {%8,%9}, {%0,%1,%2,%3};\n"             \
        : "+f"((d)[0]), "+f"((d)[1]), "+f"((d)[2]), "+f"((d)[3])              \
        : "r"(a0), "r"(a1), "r"(a2), "r"(a3), "r"(b0), "r"(b1))

// Stage layout (BK = 16): 4 stages x 16KB. Within a stage:
//   A at +0:    4 quad-regions of 2KB; row r of quad q at q*2048 + ((r ^ 2q)*16)
//   B at +8192: same layout
#define STAGE_BYTES 16384
#define NSTAGE 4
#define SMEM_GEMM (NSTAGE * STAGE_BYTES)   // 65536

// ---------------------------------------------------------------------------
// prep kernels
// ---------------------------------------------------------------------------
__global__ __launch_bounds__(256) void prep_w(const float* __restrict__ wf,
                                              const float* __restrict__ wpl) {
    int i4 = blockIdx.x * 256 + threadIdx.x;  // 1,048,576 float4
    float4 a = ((const float4*)wf)[i4];
    float4 b = ((const float4*)wpl)[i4];
    float4 s = make_float4(a.x + b.x, a.y + b.y, a.z + b.z, a.w + b.w);
    ((uint4*)g_wsum)[i4] = tf32x4(s);
}

// 32x32 tiles: write rna(x) (same layout) and rna(x)^T
__global__ __launch_bounds__(256) void prep_x(const float* __restrict__ x) {
    __shared__ float tsm[32][33];
    const int tx = threadIdx.x, ty = threadIdx.y;
    const int p0 = blockIdx.x * 32, m0 = blockIdx.y * 32;
#pragma unroll
    for (int i = 0; i < 4; i++) {
        const int m = m0 + ty + i * 8;
        float v = x[(size_t)m * H_DIM + p0 + tx];
        float r = __uint_as_float(f2tf32(v));
        g_xr[(size_t)m * H_DIM + p0 + tx] = r;
        tsm[ty + i * 8][tx] = r;
    }
    __syncthreads();
#pragma unroll
    for (int i = 0; i < 4; i++) {
        const int p = p0 + ty + i * 8;
        g_xt[(size_t)p * M_DIM + m0 + tx] = tsm[tx][ty + i * 8];
    }
}

// zero colsum, then accumulate: colsum[h] = sum_m x[m][h] (fp32, original x)
__global__ void zero_colsum() {
    g_colsum[blockIdx.x * 1024 + threadIdx.x] = 0.0f;
}
__global__ __launch_bounds__(256) void colsum_k(const float* __restrict__ x) {
    __shared__ float red[8][128];
    const int tx = threadIdx.x & 31, ty = threadIdx.x >> 5;
    const int c0 = blockIdx.x * 128;
    const int r0 = blockIdx.y * 512;
    float4 s = make_float4(0.f, 0.f, 0.f, 0.f);
    for (int m = r0 + ty; m < r0 + 512; m += 8) {
        float4 v = *(const float4*)&x[(size_t)m * H_DIM + c0 + tx * 4];
        s.x += v.x; s.y += v.y; s.z += v.z; s.w += v.w;
    }
    *(float4*)&red[ty][tx * 4] = s;
    __syncthreads();
    if (ty == 0) {
        float4 acc = make_float4(0.f, 0.f, 0.f, 0.f);
#pragma unroll
        for (int r = 0; r < 8; r++) {
            float4 v = *(const float4*)&red[r][tx * 4];
            acc.x += v.x; acc.y += v.y; acc.z += v.z; acc.w += v.w;
        }
        atomicAdd(&g_colsum[c0 + tx * 4 + 0], acc.x);
        atomicAdd(&g_colsum[c0 + tx * 4 + 1], acc.y);
        atomicAdd(&g_colsum[c0 + tx * 4 + 2], acc.z);
        atomicAdd(&g_colsum[c0 + tx * 4 + 3], acc.w);
    }
}

// ---------------------------------------------------------------------------
// core mainloop pieces (round-7 proven structure: 256 thr, 64x32 warp tiles)
// ---------------------------------------------------------------------------
struct Frags {
    uint32_t rowA16[4];
    uint32_t rowB16[2];
    uint32_t qa, qb;
};

__device__ __forceinline__ void init_frags(Frags& F, int lane, int wm, int wn) {
    const int G = lane >> 3;
#pragma unroll
    for (int mi = 0; mi < 4; mi++)
        F.rowA16[mi] = (uint32_t)(wm + mi * 16 + (lane & 15)) * 16u;
#pragma unroll
    for (int P = 0; P < 2; P++)
        F.rowB16[P] = (uint32_t)(wn + (2 * P + (G >> 1)) * 8 + (lane & 7)) * 16u;
    F.qa = (uint32_t)(lane >> 4);
    F.qb = (uint32_t)(G & 1);
}

__device__ __forceinline__ void compute_stage(const Frags& F, uint32_t stg,
                                              float acc[4][4][4]) {
#pragma unroll
    for (int ks8 = 0; ks8 < 2; ks8++) {
        const uint32_t aq = (uint32_t)(ks8 * 2) + F.qa;
        const uint32_t bq = (uint32_t)(ks8 * 2) + F.qb;
        uint32_t af[4][4], bf[2][4];
#pragma unroll
        for (int mi = 0; mi < 4; mi++)
            ldsm4(af[mi], stg + aq * 2048u + (F.rowA16[mi] ^ (aq << 5)));
#pragma unroll
        for (int P = 0; P < 2; P++)
            ldsm4(bf[P], stg + 8192u + bq * 2048u + (F.rowB16[P] ^ (bq << 5)));
#pragma unroll
        for (int mi = 0; mi < 4; mi++)
#pragma unroll
            for (int P = 0; P < 2; P++) {
                MMA_TF32(acc[mi][2 * P],     af[mi][0], af[mi][1], af[mi][2], af[mi][3],
                         bf[P][0], bf[P][1]);
                MMA_TF32(acc[mi][2 * P + 1], af[mi][0], af[mi][1], af[mi][2], af[mi][3],
                         bf[P][2], bf[P][3]);
            }
    }
}

#define ISSUE_STAGE(kt, gA0, gA1, gB0, gB1, sA0)  do {                     \
        const uint32_t st_ = (uint32_t)((kt) & (NSTAGE - 1)) * STAGE_BYTES; \
        const size_t ko_ = (size_t)(kt) * 16;                              \
        cp16((sA0) + st_,          (gA0) + ko_);                           \
        cp16((sA0) + st_ + 1024u,  (gA1) + ko_);                           \
        cp16((sA0) + st_ + 8192u,  (gB0) + ko_);                           \
        cp16((sA0) + st_ + 9216u,  (gB1) + ko_);                           \
    } while (0)

#define MAINLOOP(KT, gA0, gA1, gB0, gB1, sA0, sbase, F, acc)  do {         \
        ISSUE_STAGE(0, gA0, gA1, gB0, gB1, sA0); CP_COMMIT();              \
        ISSUE_STAGE(1, gA0, gA1, gB0, gB1, sA0); CP_COMMIT();              \
        ISSUE_STAGE(2, gA0, gA1, gB0, gB1, sA0); CP_COMMIT();              \
        for (int kt = 0; kt < (KT); kt++) {                                \
            CP_WAIT2();                                                    \
            __syncthreads();                                               \
            if (kt + 3 < (KT)) { ISSUE_STAGE(kt + 3, gA0, gA1, gB0, gB1, sA0); } \
            CP_COMMIT();                                                   \
            compute_stage(F, (sbase) + (uint32_t)(kt & (NSTAGE - 1)) * STAGE_BYTES, acc); \
        }                                                                  \
    } while (0)

// ---------------------------------------------------------------------------
// GEMM1: combined[m,n] = g_xr[m,:] . g_wsum[n,:] + bias[n]
// ---------------------------------------------------------------------------
__global__ __launch_bounds__(256, 2) void gemm1_k(
    const float* __restrict__ bias, float* __restrict__ C)
{
    extern __shared__ char sm[];
    const uint32_t sbase = smem_u32(sm);
    const int tid = threadIdx.x, lane = tid & 31, warp = tid >> 5;
    const int g = lane >> 2, t = lane & 3;
    const int wm = (warp >> 2) * 64, wn = (warp & 3) * 32;
    const int m0 = blockIdx.y * 128, n0 = blockIdx.x * 128;

    const int lq = tid & 3, lr = tid >> 2;
    const float* gA0 = g_xr   + (size_t)(m0 + lr) * H_DIM + lq * 4;
    const float* gA1 = gA0 + (size_t)64 * H_DIM;
    const float* gB0 = g_wsum + (size_t)(n0 + lr) * H_DIM + lq * 4;
    const float* gB1 = gB0 + (size_t)64 * H_DIM;
    const uint32_t sA0 = sbase + (uint32_t)lq * 2048u + (uint32_t)((lr ^ (2 * lq)) * 16);

    Frags F;
    init_frags(F, lane, wm, wn);

    float acc[4][4][4];
#pragma unroll
    for (int mi = 0; mi < 4; mi++)
#pragma unroll
        for (int ni = 0; ni < 4; ni++)
#pragma unroll
            for (int c = 0; c < 4; c++) acc[mi][ni][c] = 0.0f;

    MAINLOOP(H_DIM / 16, gA0, gA1, gB0, gB1, sA0, sbase, F, acc);

#pragma unroll
    for (int ni = 0; ni < 4; ni++) {
        const int n = wn + ni * 8 + 2 * t;
        const float2 bv = *(const float2*)&bias[n0 + n];
#pragma unroll
        for (int mi = 0; mi < 4; mi++) {
            const int m = wm + mi * 16 + g;
            *(float2*)&C[(size_t)(m0 + m) * H_DIM + n0 + n] =
                make_float2(acc[mi][ni][0] + bv.x, acc[mi][ni][1] + bv.y);
            *(float2*)&C[(size_t)(m0 + m + 8) * H_DIM + n0 + n] =
                make_float2(acc[mi][ni][2] + bv.x, acc[mi][ni][3] + bv.y);
        }
    }
}

// ---------------------------------------------------------------------------
// Gram (split-K=8, lower-triangle blocks): g_gp[sp][p,q] = sum_{m in split} xt[p,m]*xt[q,m]
// ---------------------------------------------------------------------------
__global__ __launch_bounds__(256, 2) void gram_k()
{
    extern __shared__ char sm[];
    const uint32_t sbase = smem_u32(sm);
    const int tid = threadIdx.x, lane = tid & 31, warp = tid >> 5;
    const int g = lane >> 2, t = lane & 3;
    const int wm = (warp >> 2) * 64, wn = (warp & 3) * 32;

    // triangle mapping: blockIdx.x in [0,136) -> (bx, by) with by >= bx
    const int tt = blockIdx.x;
    int by = (int)((sqrtf(8.0f * (float)tt + 1.0f) - 1.0f) * 0.5f);
    while ((by + 1) * (by + 2) / 2 <= tt) by++;
    while (by * (by + 1) / 2 > tt) by--;
    const int bx = tt - by * (by + 1) / 2;

    const int p0 = by * 128, q0 = bx * 128;
    const int sp = blockIdx.y;                 // 0..7
    const int mbase = sp * (M_DIM / 8);        // 2048 per split

    const int lq = tid & 3, lr = tid >> 2;
    const float* gA0 = g_xt + (size_t)(p0 + lr) * M_DIM + mbase + lq * 4;
    const float* gA1 = gA0 + (size_t)64 * M_DIM;
    const float* gB0 = g_xt + (size_t)(q0 + lr) * M_DIM + mbase + lq * 4;
    const float* gB1 = gB0 + (size_t)64 * M_DIM;
    const uint32_t sA0 = sbase + (uint32_t)lq * 2048u + (uint32_t)((lr ^ (2 * lq)) * 16);

    Frags F;
    init_frags(F, lane, wm, wn);

    float acc[4][4][4];
#pragma unroll
    for (int mi = 0; mi < 4; mi++)
#pragma unroll
        for (int ni = 0; ni < 4; ni++)
#pragma unroll
            for (int c = 0; c < 4; c++) acc[mi][ni][c] = 0.0f;

    MAINLOOP((M_DIM / 8) / 16, gA0, gA1, gB0, gB1, sA0, sbase, F, acc);

    float* dst = g_gp[sp];
#pragma unroll
    for (int ni = 0; ni < 4; ni++) {
        const int q = q0 + wn + ni * 8 + 2 * t;
#pragma unroll
        for (int mi = 0; mi < 4; mi++) {
            const int p = p0 + wm + mi * 16 + g;
            *(float2*)&dst[(size_t)p * H_DIM + q]       = make_float2(acc[mi][ni][0], acc[mi][ni][1]);
            *(float2*)&dst[(size_t)(p + 8) * H_DIM + q] = make_float2(acc[mi][ni][2], acc[mi][ni][3]);
        }
    }
}

// ---------------------------------------------------------------------------
// Mirror: g_gram[i][j] = g_gram[j][i] = rna(sum_sp g_gp[sp][i][j])  for i >= j
// ---------------------------------------------------------------------------
__global__ __launch_bounds__(128) void mirror_k() {
    const int i = blockIdx.y;
    const int j = blockIdx.x * 128 + threadIdx.x;
    if (j > i) return;
    const size_t idx = (size_t)i * H_DIM + j;
    float s = 0.0f;
#pragma unroll
    for (int sp = 0; sp < 8; sp++) s += g_gp[sp][idx];
    const float r = __uint_as_float(f2tf32(s));
    g_gram[idx] = r;
    g_gram[(size_t)j * H_DIM + i] = r;
}

// ---------------------------------------------------------------------------
// hebb GEMM + fused output: outw[p,q] = wp[p,q] + f*(G[p,:].wsum[q,:] + colsum[p]*b[q])
// Also emits per-block ssq partials.
// ---------------------------------------------------------------------------
__global__ __launch_bounds__(256, 2) void hebb_k(
    const float* __restrict__ wpl, const float* __restrict__ pr,
    const float* __restrict__ hs, const float* __restrict__ bias,
    float* __restrict__ outw)
{
    extern __shared__ char sm[];
    __shared__ float red[8];
    const uint32_t sbase = smem_u32(sm);
    const int tid = threadIdx.x, lane = tid & 31, warp = tid >> 5;
    const int g = lane >> 2, t = lane & 3;
    const int wm = (warp >> 2) * 64, wn = (warp & 3) * 32;
    const int p0 = blockIdx.y * 128, q0 = blockIdx.x * 128;

    const int lq = tid & 3, lr = tid >> 2;
    const float* gA0 = g_gram + (size_t)(p0 + lr) * H_DIM + lq * 4;
    const float* gA1 = gA0 + (size_t)64 * H_DIM;
    const float* gB0 = g_wsum + (size_t)(q0 + lr) * H_DIM + lq * 4;
    const float* gB1 = gB0 + (size_t)64 * H_DIM;
    const uint32_t sA0 = sbase + (uint32_t)lq * 2048u + (uint32_t)((lr ^ (2 * lq)) * 16);

    Frags F;
    init_frags(F, lane, wm, wn);

    float acc[4][4][4];
#pragma unroll
    for (int mi = 0; mi < 4; mi++)
#pragma unroll
        for (int ni = 0; ni < 4; ni++)
#pragma unroll
            for (int c = 0; c < 4; c++) acc[mi][ni][c] = 0.0f;

    MAINLOOP(H_DIM / 16, gA0, gA1, gB0, gB1, sA0, sbase, F, acc);

    const float f = pr[0] * hs[0] * (1.0f / (float)M_DIM);
    float ssq = 0.0f;
#pragma unroll
    for (int ni = 0; ni < 4; ni++) {
        const int q = q0 + wn + ni * 8 + 2 * t;
        const float2 bv = *(const float2*)&bias[q];
#pragma unroll
        for (int mi = 0; mi < 4; mi++) {
            const int p = p0 + wm + mi * 16 + g;
            const float cs0 = g_colsum[p], cs1 = g_colsum[p + 8];
            {
                float2 w = *(const float2*)&wpl[(size_t)p * H_DIM + q];
                float2 v = make_float2(w.x + f * (acc[mi][ni][0] + cs0 * bv.x),
                                       w.y + f * (acc[mi][ni][1] + cs0 * bv.y));
                *(float2*)&outw[(size_t)p * H_DIM + q] = v;
                ssq += v.x * v.x + v.y * v.y;
            }
            {
                float2 w = *(const float2*)&wpl[(size_t)(p + 8) * H_DIM + q];
                float2 v = make_float2(w.x + f * (acc[mi][ni][2] + cs1 * bv.x),
                                       w.y + f * (acc[mi][ni][3] + cs1 * bv.y));
                *(float2*)&outw[(size_t)(p + 8) * H_DIM + q] = v;
                ssq += v.x * v.x + v.y * v.y;
            }
        }
    }

#pragma unroll
    for (int o = 16; o; o >>= 1) ssq += __shfl_xor_sync(0xffffffffu, ssq, o);
    if (lane == 0) red[warp] = ssq;
    __syncthreads();
    if (tid == 0) {
        float s = 0.0f;
#pragma unroll
        for (int w = 0; w < 8; w++) s += red[w];
        g_partials[blockIdx.y * gridDim.x + blockIdx.x] = s;
    }
}

// ---------------------------------------------------------------------------
// Frobenius norm finalize + conditional scale
// ---------------------------------------------------------------------------
__global__ void finalize_kernel() {
    const int tid = threadIdx.x;
    __shared__ float red[8];
    float v = g_partials[tid];
#pragma unroll
    for (int o = 16; o; o >>= 1) v += __shfl_xor_sync(0xffffffffu, v, o);
    if ((tid & 31) == 0) red[tid >> 5] = v;
    __syncthreads();
    if (tid == 0) {
        float s = 0.0f;
#pragma unroll
        for (int w = 0; w < 8; w++) s += red[w];
        const float n = sqrtf(s);
        g_scale = (n > 1.0f) ? (1.0f / n) : 1.0f;
    }
}

__global__ void scale_kernel(float* __restrict__ w) {
    const float s = g_scale;
    const int n4 = (H_DIM * H_DIM) / 4;
    float4* w4 = (float4*)w;
    for (int i = blockIdx.x * blockDim.x + threadIdx.x; i < n4;
         i += gridDim.x * blockDim.x) {
        float4 v = w4[i];
        v.x *= s; v.y *= s; v.z *= s; v.w *= s;
        w4[i] = v;
    }
}

// ---------------------------------------------------------------------------
// Inputs: x, plastic_weights, plasticity_rate, fixed_w, fixed_b, hebbian_strength
// Output: combined [16384,2048] ++ new_w [2048,2048]
// ---------------------------------------------------------------------------
extern "C" void kernel_launch(void* const* d_in, const int* in_sizes, int n_in,
                              void* d_out, int out_size)
{
    const float* x  = (const float*)d_in[0];
    const float* wp = (const float*)d_in[1];
    const float* pr = (const float*)d_in[2];
    const float* wf = (const float*)d_in[3];
    const float* fb = (const float*)d_in[4];
    const float* hs = (const float*)d_in[5];

    float* combined = (float*)d_out;
    float* outw     = combined + (size_t)M_DIM * H_DIM;

    cudaFuncSetAttribute(gemm1_k, cudaFuncAttributeMaxDynamicSharedMemorySize, SMEM_GEMM);
    cudaFuncSetAttribute(gram_k,  cudaFuncAttributeMaxDynamicSharedMemorySize, SMEM_GEMM);
    cudaFuncSetAttribute(hebb_k,  cudaFuncAttributeMaxDynamicSharedMemorySize, SMEM_GEMM);

    prep_w<<<4096, 256>>>(wf, wp);
    prep_x<<<dim3(H_DIM / 32, M_DIM / 32), dim3(32, 8)>>>(x);
    zero_colsum<<<2, 1024>>>();
    colsum_k<<<dim3(16, 32), 256>>>(x);

    gram_k<<<dim3(136, 8), 256, SMEM_GEMM>>>();
    gemm1_k<<<dim3(16, 128), 256, SMEM_GEMM>>>(fb, combined);
    mirror_k<<<dim3(16, 2048), 128>>>();
    hebb_k<<<dim3(16, 16), 256, SMEM_GEMM>>>(wp, pr, hs, fb, outw);

    finalize_kernel<<<1, 256>>>();
    scale_kernel<<<2048, 256>>>(outw);
}

// round 16
// speedup vs baseline: 1.4430x; 1.0112x over previous
#include <cuda_runtime.h>
#include <stdint.h>
#include <math.h>

// Problem shape (fixed by dataset): B=8, S=2048, H=2048
#define M_DIM 16384
#define H_DIM 2048

// Static device scratch (allowed; no runtime allocation)
__device__ float g_xr[(size_t)M_DIM * H_DIM];    // rna(x)         [m][h]
__device__ float g_xt[(size_t)H_DIM * M_DIM];    // rna(x)^T       [h][m]
__device__ float g_wsum[(size_t)H_DIM * H_DIM];  // rna(Wf + Wp)   [n][k]
__device__ float g_gp[4][(size_t)H_DIM * H_DIM]; // Gram split-K partials (lower-tri blocks)
__device__ float g_gram[(size_t)H_DIM * H_DIM];  // rna(x^T x), full (mirrored)
__device__ float g_colsum[H_DIM];                // sum_m x[m][h]
__device__ float g_partials[256];
__device__ float g_scale;

// ---------------------------------------------------------------------------
// helpers
// ---------------------------------------------------------------------------
__device__ __forceinline__ uint32_t smem_u32(const void* p) {
    uint32_t a;
    asm("{ .reg .u64 t; cvta.to.shared.u64 t, %1; cvt.u32.u64 %0, t; }" : "=r"(a) : "l"(p));
    return a;
}
__device__ __forceinline__ uint32_t f2tf32(float f) {
    uint32_t r;
    asm("cvt.rna.tf32.f32 %0, %1;" : "=r"(r) : "f"(f));
    return r;
}
__device__ __forceinline__ uint4 tf32x4(float4 v) {
    uint4 r;
    r.x = f2tf32(v.x); r.y = f2tf32(v.y); r.z = f2tf32(v.z); r.w = f2tf32(v.w);
    return r;
}
__device__ __forceinline__ void cp16(uint32_t s, const void* g) {
    asm volatile("cp.async.cg.shared.global [%0], [%1], 16;" :: "r"(s), "l"(g) : "memory");
}
#define CP_COMMIT() asm volatile("cp.async.commit_group;" ::: "memory")
#define CP_WAIT2()  asm volatile("cp.async.wait_group 2;" ::: "memory")

__device__ __forceinline__ void ldsm4(uint32_t* r, uint32_t addr) {
    asm volatile("ldmatrix.sync.aligned.m8n8.x4.shared.b16 {%0,%1,%2,%3}, [%4];"
                 : "=r"(r[0]), "=r"(r[1]), "=r"(r[2]), "=r"(r[3]) : "r"(addr));
}

#define MMA_TF32(d, a0, a1, a2, a3, b0, b1)                                   \
    asm volatile(                                                             \
        "mma.sync.aligned.m16n8k8.row.col.f32.tf32.tf32.f32 "                 \
        "{%0,%1,%2,%3}, {%4,%5,%6,%7}, {%8,%9}, {%0,%1,%2,%3};\n"             \
        : "+f"((d)[0]), "+f"((d)[1]), "+f"((d)[2]), "+f"((d)[3])              \
        : "r"(a0), "r"(a1), "r"(a2), "r"(a3), "r"(b0), "r"(b1))

// Stage layout (BK = 16): 4 stages x 16KB. Within a stage:
//   A at +0:    4 quad-regions of 2KB; row r of quad q at q*2048 + ((r ^ 2q)*16)
//   B at +8192: same layout
#define STAGE_BYTES 16384
#define NSTAGE 4
#define SMEM_GEMM (NSTAGE * STAGE_BYTES)   // 65536

// ---------------------------------------------------------------------------
// prep kernels
// ---------------------------------------------------------------------------
__global__ __launch_bounds__(256) void prep_w(const float* __restrict__ wf,
                                              const float* __restrict__ wpl) {
    int i4 = blockIdx.x * 256 + threadIdx.x;  // 1,048,576 float4
    float4 a = ((const float4*)wf)[i4];
    float4 b = ((const float4*)wpl)[i4];
    float4 s = make_float4(a.x + b.x, a.y + b.y, a.z + b.z, a.w + b.w);
    ((uint4*)g_wsum)[i4] = tf32x4(s);
}

__global__ void zero_colsum() {
    g_colsum[blockIdx.x * 1024 + threadIdx.x] = 0.0f;
}

// 32x32 tiles: write rna(x) (same layout), rna(x)^T, and fused column sums
__global__ __launch_bounds__(256) void prep_x(const float* __restrict__ x) {
    __shared__ float tsm[32][33];
    __shared__ float red[8][32];
    const int tx = threadIdx.x, ty = threadIdx.y;
    const int p0 = blockIdx.x * 32, m0 = blockIdx.y * 32;
#pragma unroll
    for (int i = 0; i < 4; i++) {
        const int m = m0 + ty + i * 8;
        float v = x[(size_t)m * H_DIM + p0 + tx];
        float r = __uint_as_float(f2tf32(v));
        g_xr[(size_t)m * H_DIM + p0 + tx] = r;
        tsm[ty + i * 8][tx] = r;
    }
    __syncthreads();
    // transpose store
#pragma unroll
    for (int i = 0; i < 4; i++) {
        const int p = p0 + ty + i * 8;
        g_xt[(size_t)p * M_DIM + m0 + tx] = tsm[tx][ty + i * 8];
    }
    // fused column-sum: each (tx,ty) sums 4 rows of column tx
    {
        float s = tsm[ty][tx] + tsm[ty + 8][tx] + tsm[ty + 16][tx] + tsm[ty + 24][tx];
        red[ty][tx] = s;
    }
    __syncthreads();
    if (ty == 0) {
        float s = 0.0f;
#pragma unroll
        for (int r = 0; r < 8; r++) s += red[r][tx];
        atomicAdd(&g_colsum[p0 + tx], s);
    }
}

// ---------------------------------------------------------------------------
// core mainloop pieces (round-7 proven structure: 256 thr, 64x32 warp tiles)
// ---------------------------------------------------------------------------
struct Frags {
    uint32_t rowA16[4];
    uint32_t rowB16[2];
    uint32_t qa, qb;
};

__device__ __forceinline__ void init_frags(Frags& F, int lane, int wm, int wn) {
    const int G = lane >> 3;
#pragma unroll
    for (int mi = 0; mi < 4; mi++)
        F.rowA16[mi] = (uint32_t)(wm + mi * 16 + (lane & 15)) * 16u;
#pragma unroll
    for (int P = 0; P < 2; P++)
        F.rowB16[P] = (uint32_t)(wn + (2 * P + (G >> 1)) * 8 + (lane & 7)) * 16u;
    F.qa = (uint32_t)(lane >> 4);
    F.qb = (uint32_t)(G & 1);
}

__device__ __forceinline__ void compute_stage(const Frags& F, uint32_t stg,
                                              float acc[4][4][4]) {
#pragma unroll
    for (int ks8 = 0; ks8 < 2; ks8++) {
        const uint32_t aq = (uint32_t)(ks8 * 2) + F.qa;
        const uint32_t bq = (uint32_t)(ks8 * 2) + F.qb;
        uint32_t af[4][4], bf[2][4];
#pragma unroll
        for (int mi = 0; mi < 4; mi++)
            ldsm4(af[mi], stg + aq * 2048u + (F.rowA16[mi] ^ (aq << 5)));
#pragma unroll
        for (int P = 0; P < 2; P++)
            ldsm4(bf[P], stg + 8192u + bq * 2048u + (F.rowB16[P] ^ (bq << 5)));
#pragma unroll
        for (int mi = 0; mi < 4; mi++)
#pragma unroll
            for (int P = 0; P < 2; P++) {
                MMA_TF32(acc[mi][2 * P],     af[mi][0], af[mi][1], af[mi][2], af[mi][3],
                         bf[P][0], bf[P][1]);
                MMA_TF32(acc[mi][2 * P + 1], af[mi][0], af[mi][1], af[mi][2], af[mi][3],
                         bf[P][2], bf[P][3]);
            }
    }
}

#define ISSUE_STAGE(kt, gA0, gA1, gB0, gB1, sA0)  do {                     \
        const uint32_t st_ = (uint32_t)((kt) & (NSTAGE - 1)) * STAGE_BYTES; \
        const size_t ko_ = (size_t)(kt) * 16;                              \
        cp16((sA0) + st_,          (gA0) + ko_);                           \
        cp16((sA0) + st_ + 1024u,  (gA1) + ko_);                           \
        cp16((sA0) + st_ + 8192u,  (gB0) + ko_);                           \
        cp16((sA0) + st_ + 9216u,  (gB1) + ko_);                           \
    } while (0)

#define MAINLOOP(KT, gA0, gA1, gB0, gB1, sA0, sbase, F, acc)  do {         \
        ISSUE_STAGE(0, gA0, gA1, gB0, gB1, sA0); CP_COMMIT();              \
        ISSUE_STAGE(1, gA0, gA1, gB0, gB1, sA0); CP_COMMIT();              \
        ISSUE_STAGE(2, gA0, gA1, gB0, gB1, sA0); CP_COMMIT();              \
        for (int kt = 0; kt < (KT); kt++) {                                \
            CP_WAIT2();                                                    \
            __syncthreads();                                               \
            if (kt + 3 < (KT)) { ISSUE_STAGE(kt + 3, gA0, gA1, gB0, gB1, sA0); } \
            CP_COMMIT();                                                   \
            compute_stage(F, (sbase) + (uint32_t)(kt & (NSTAGE - 1)) * STAGE_BYTES, acc); \
        }                                                                  \
    } while (0)

// ---------------------------------------------------------------------------
// GEMM1: combined[m,n] = g_xr[m,:] . g_wsum[n,:] + bias[n]
// ---------------------------------------------------------------------------
__global__ __launch_bounds__(256, 2) void gemm1_k(
    const float* __restrict__ bias, float* __restrict__ C)
{
    extern __shared__ char sm[];
    const uint32_t sbase = smem_u32(sm);
    const int tid = threadIdx.x, lane = tid & 31, warp = tid >> 5;
    const int g = lane >> 2, t = lane & 3;
    const int wm = (warp >> 2) * 64, wn = (warp & 3) * 32;
    const int m0 = blockIdx.y * 128, n0 = blockIdx.x * 128;

    const int lq = tid & 3, lr = tid >> 2;
    const float* gA0 = g_xr   + (size_t)(m0 + lr) * H_DIM + lq * 4;
    const float* gA1 = gA0 + (size_t)64 * H_DIM;
    const float* gB0 = g_wsum + (size_t)(n0 + lr) * H_DIM + lq * 4;
    const float* gB1 = gB0 + (size_t)64 * H_DIM;
    const uint32_t sA0 = sbase + (uint32_t)lq * 2048u + (uint32_t)((lr ^ (2 * lq)) * 16);

    Frags F;
    init_frags(F, lane, wm, wn);

    float acc[4][4][4];
#pragma unroll
    for (int mi = 0; mi < 4; mi++)
#pragma unroll
        for (int ni = 0; ni < 4; ni++)
#pragma unroll
            for (int c = 0; c < 4; c++) acc[mi][ni][c] = 0.0f;

    MAINLOOP(H_DIM / 16, gA0, gA1, gB0, gB1, sA0, sbase, F, acc);

#pragma unroll
    for (int ni = 0; ni < 4; ni++) {
        const int n = wn + ni * 8 + 2 * t;
        const float2 bv = *(const float2*)&bias[n0 + n];
#pragma unroll
        for (int mi = 0; mi < 4; mi++) {
            const int m = wm + mi * 16 + g;
            *(float2*)&C[(size_t)(m0 + m) * H_DIM + n0 + n] =
                make_float2(acc[mi][ni][0] + bv.x, acc[mi][ni][1] + bv.y);
            *(float2*)&C[(size_t)(m0 + m + 8) * H_DIM + n0 + n] =
                make_float2(acc[mi][ni][2] + bv.x, acc[mi][ni][3] + bv.y);
        }
    }
}

// ---------------------------------------------------------------------------
// Gram (split-K=4, lower-triangle blocks): g_gp[sp][p,q] = sum_{m in split} xt[p,m]*xt[q,m]
// ---------------------------------------------------------------------------
__global__ __launch_bounds__(256, 2) void gram_k()
{
    extern __shared__ char sm[];
    const uint32_t sbase = smem_u32(sm);
    const int tid = threadIdx.x, lane = tid & 31, warp = tid >> 5;
    const int g = lane >> 2, t = lane & 3;
    const int wm = (warp >> 2) * 64, wn = (warp & 3) * 32;

    // triangle mapping: blockIdx.x in [0,136) -> (bx, by) with by >= bx
    const int tt = blockIdx.x;
    int by = (int)((sqrtf(8.0f * (float)tt + 1.0f) - 1.0f) * 0.5f);
    while ((by + 1) * (by + 2) / 2 <= tt) by++;
    while (by * (by + 1) / 2 > tt) by--;
    const int bx = tt - by * (by + 1) / 2;

    const int p0 = by * 128, q0 = bx * 128;
    const int sp = blockIdx.y;                 // 0..3
    const int mbase = sp * (M_DIM / 4);        // 4096 per split

    const int lq = tid & 3, lr = tid >> 2;
    const float* gA0 = g_xt + (size_t)(p0 + lr) * M_DIM + mbase + lq * 4;
    const float* gA1 = gA0 + (size_t)64 * M_DIM;
    const float* gB0 = g_xt + (size_t)(q0 + lr) * M_DIM + mbase + lq * 4;
    const float* gB1 = gB0 + (size_t)64 * M_DIM;
    const uint32_t sA0 = sbase + (uint32_t)lq * 2048u + (uint32_t)((lr ^ (2 * lq)) * 16);

    Frags F;
    init_frags(F, lane, wm, wn);

    float acc[4][4][4];
#pragma unroll
    for (int mi = 0; mi < 4; mi++)
#pragma unroll
        for (int ni = 0; ni < 4; ni++)
#pragma unroll
            for (int c = 0; c < 4; c++) acc[mi][ni][c] = 0.0f;

    MAINLOOP((M_DIM / 4) / 16, gA0, gA1, gB0, gB1, sA0, sbase, F, acc);

    float* dst = g_gp[sp];
#pragma unroll
    for (int ni = 0; ni < 4; ni++) {
        const int q = q0 + wn + ni * 8 + 2 * t;
#pragma unroll
        for (int mi = 0; mi < 4; mi++) {
            const int p = p0 + wm + mi * 16 + g;
            *(float2*)&dst[(size_t)p * H_DIM + q]       = make_float2(acc[mi][ni][0], acc[mi][ni][1]);
            *(float2*)&dst[(size_t)(p + 8) * H_DIM + q] = make_float2(acc[mi][ni][2], acc[mi][ni][3]);
        }
    }
}

// ---------------------------------------------------------------------------
// Mirror: g_gram[i][j] = g_gram[j][i] = rna(sum_sp g_gp[sp][i][j])  for i >= j
// ---------------------------------------------------------------------------
__global__ __launch_bounds__(128) void mirror_k() {
    const int i = blockIdx.y;
    const int j = blockIdx.x * 128 + threadIdx.x;
    if (j > i) return;
    const size_t idx = (size_t)i * H_DIM + j;
    float s = 0.0f;
#pragma unroll
    for (int sp = 0; sp < 4; sp++) s += g_gp[sp][idx];
    const float r = __uint_as_float(f2tf32(s));
    g_gram[idx] = r;
    g_gram[(size_t)j * H_DIM + i] = r;
}

// ---------------------------------------------------------------------------
// hebb GEMM + fused output: outw[p,q] = wp[p,q] + f*(G[p,:].wsum[q,:] + colsum[p]*b[q])
// Also emits per-block ssq partials.
// ---------------------------------------------------------------------------
__global__ __launch_bounds__(256, 2) void hebb_k(
    const float* __restrict__ wpl, const float* __restrict__ pr,
    const float* __restrict__ hs, const float* __restrict__ bias,
    float* __restrict__ outw)
{
    extern __shared__ char sm[];
    __shared__ float red[8];
    const uint32_t sbase = smem_u32(sm);
    const int tid = threadIdx.x, lane = tid & 31, warp = tid >> 5;
    const int g = lane >> 2, t = lane & 3;
    const int wm = (warp >> 2) * 64, wn = (warp & 3) * 32;
    const int p0 = blockIdx.y * 128, q0 = blockIdx.x * 128;

    const int lq = tid & 3, lr = tid >> 2;
    const float* gA0 = g_gram + (size_t)(p0 + lr) * H_DIM + lq * 4;
    const float* gA1 = gA0 + (size_t)64 * H_DIM;
    const float* gB0 = g_wsum + (size_t)(q0 + lr) * H_DIM + lq * 4;
    const float* gB1 = gB0 + (size_t)64 * H_DIM;
    const uint32_t sA0 = sbase + (uint32_t)lq * 2048u + (uint32_t)((lr ^ (2 * lq)) * 16);

    Frags F;
    init_frags(F, lane, wm, wn);

    float acc[4][4][4];
#pragma unroll
    for (int mi = 0; mi < 4; mi++)
#pragma unroll
        for (int ni = 0; ni < 4; ni++)
#pragma unroll
            for (int c = 0; c < 4; c++) acc[mi][ni][c] = 0.0f;

    MAINLOOP(H_DIM / 16, gA0, gA1, gB0, gB1, sA0, sbase, F, acc);

    const float f = pr[0] * hs[0] * (1.0f / (float)M_DIM);
    float ssq = 0.0f;
#pragma unroll
    for (int ni = 0; ni < 4; ni++) {
        const int q = q0 + wn + ni * 8 + 2 * t;
        const float2 bv = *(const float2*)&bias[q];
#pragma unroll
        for (int mi = 0; mi < 4; mi++) {
            const int p = p0 + wm + mi * 16 + g;
            const float cs0 = g_colsum[p], cs1 = g_colsum[p + 8];
            {
                float2 w = *(const float2*)&wpl[(size_t)p * H_DIM + q];
                float2 v = make_float2(w.x + f * (acc[mi][ni][0] + cs0 * bv.x),
                                       w.y + f * (acc[mi][ni][1] + cs0 * bv.y));
                *(float2*)&outw[(size_t)p * H_DIM + q] = v;
                ssq += v.x * v.x + v.y * v.y;
            }
            {
                float2 w = *(const float2*)&wpl[(size_t)(p + 8) * H_DIM + q];
                float2 v = make_float2(w.x + f * (acc[mi][ni][2] + cs1 * bv.x),
                                       w.y + f * (acc[mi][ni][3] + cs1 * bv.y));
                *(float2*)&outw[(size_t)(p + 8) * H_DIM + q] = v;
                ssq += v.x * v.x + v.y * v.y;
            }
        }
    }

#pragma unroll
    for (int o = 16; o; o >>= 1) ssq += __shfl_xor_sync(0xffffffffu, ssq, o);
    if (lane == 0) red[warp] = ssq;
    __syncthreads();
    if (tid == 0) {
        float s = 0.0f;
#pragma unroll
        for (int w = 0; w < 8; w++) s += red[w];
        g_partials[blockIdx.y * gridDim.x + blockIdx.x] = s;
    }
}

// ---------------------------------------------------------------------------
// Frobenius norm finalize + conditional scale
// ---------------------------------------------------------------------------
__global__ void finalize_kernel() {
    const int tid = threadIdx.x;
    __shared__ float red[8];
    float v = g_partials[tid];
#pragma unroll
    for (int o = 16; o; o >>= 1) v += __shfl_xor_sync(0xffffffffu, v, o);
    if ((tid & 31) == 0) red[tid >> 5] = v;
    __syncthreads();
    if (tid == 0) {
        float s = 0.0f;
#pragma unroll
        for (int w = 0; w < 8; w++) s += red[w];
        const float n = sqrtf(s);
        g_scale = (n > 1.0f) ? (1.0f / n) : 1.0f;
    }
}

__global__ void scale_kernel(float* __restrict__ w) {
    const float s = g_scale;
    const int n4 = (H_DIM * H_DIM) / 4;
    float4* w4 = (float4*)w;
    for (int i = blockIdx.x * blockDim.x + threadIdx.x; i < n4;
         i += gridDim.x * blockDim.x) {
        float4 v = w4[i];
        v.x *= s; v.y *= s; v.z *= s; v.w *= s;
        w4[i] = v;
    }
}

// ---------------------------------------------------------------------------
// Inputs: x, plastic_weights, plasticity_rate, fixed_w, fixed_b, hebbian_strength
// Output: combined [16384,2048] ++ new_w [2048,2048]
// ---------------------------------------------------------------------------
extern "C" void kernel_launch(void* const* d_in, const int* in_sizes, int n_in,
                              void* d_out, int out_size)
{
    const float* x  = (const float*)d_in[0];
    const float* wp = (const float*)d_in[1];
    const float* pr = (const float*)d_in[2];
    const float* wf = (const float*)d_in[3];
    const float* fb = (const float*)d_in[4];
    const float* hs = (const float*)d_in[5];

    float* combined = (float*)d_out;
    float* outw     = combined + (size_t)M_DIM * H_DIM;

    cudaFuncSetAttribute(gemm1_k, cudaFuncAttributeMaxDynamicSharedMemorySize, SMEM_GEMM);
    cudaFuncSetAttribute(gram_k,  cudaFuncAttributeMaxDynamicSharedMemorySize, SMEM_GEMM);
    cudaFuncSetAttribute(hebb_k,  cudaFuncAttributeMaxDynamicSharedMemorySize, SMEM_GEMM);

    prep_w<<<4096, 256>>>(wf, wp);
    zero_colsum<<<2, 1024>>>();
    prep_x<<<dim3(H_DIM / 32, M_DIM / 32), dim3(32, 8)>>>(x);

    gram_k<<<dim3(136, 4), 256, SMEM_GEMM>>>();
    gemm1_k<<<dim3(16, 128), 256, SMEM_GEMM>>>(fb, combined);
    mirror_k<<<dim3(16, 2048), 128>>>();
    hebb_k<<<dim3(16, 16), 256, SMEM_GEMM>>>(wp, pr, hs, fb, outw);

    finalize_kernel<<<1, 256>>>();
    scale_kernel<<<2048, 256>>>(outw);
}